// round 15
// baseline (speedup 1.0000x reference)
#include <cuda_runtime.h>
#include <cuda_fp16.h>
#include <math.h>

// ---------------------------------------------------------------------------
// AttentiveBimodalCSRPool — round 15.
//   R14 kernels (best 889us family) + validated launch consolidation:
//   front(seg+zero+prep), cov(+bn1 in last block), fused12(+bn2 in last
//   block), R(+c blocks), score, pool.  10 launches -> 6.
// ---------------------------------------------------------------------------

#define MAXV 1000000
#define MAXN 125056
typedef unsigned long long ull;

__device__ __align__(16) unsigned short g_Y2h[(size_t)MAXV * 64];  // fp16
__device__ float g_R[(size_t)MAXN * 192];
__device__ float g_c[MAXN];
__device__ float g_X[MAXV];
__device__ int   g_seg[MAXV];
__device__ float g_stats[256];    // [128..191]=sum2, [192..255]=sq2
__device__ float g_cov[32 * 32];
__device__ float g_mu[32];
__device__ float g_bn1[128];      // [scale(64), shift(64)]
__device__ float g_bn2[128];
__device__ float g_Acmb[64 * 192];
__device__ float g_r0[192];
__device__ float g_wc[64];
__device__ float g_c0[1];
__device__ int   g_ctr[2];        // [0]=cov blocks done, [1]=fused12 blocks done

// ---- packed f32x2 helpers -------------------------------------------------
__device__ __forceinline__ ull pk2(float lo, float hi) {
    ull r; asm("mov.b64 %0, {%1, %2};" : "=l"(r) : "f"(lo), "f"(hi)); return r;
}
__device__ __forceinline__ ull fma2(ull a, ull b, ull c) {
    ull d; asm("fma.rn.f32x2 %0, %1, %2, %3;" : "=l"(d) : "l"(a), "l"(b), "l"(c));
    return d;
}
__device__ __forceinline__ void upk2(ull v, float& lo, float& hi) {
    asm("mov.b64 {%0, %1}, %2;" : "=f"(lo), "=f"(hi) : "l"(v));
}

// ---- row-major tile loader: sX[r][k], LD odd => conflict-free -------------
template <int K, int LD, int NT>
__device__ __forceinline__ void load_rm(const float* __restrict__ src,
                                        int row0, int limit,
                                        int srcStride, int srcOff,
                                        float* __restrict__ sX, int tid) {
    constexpr int K4 = K / 4;
    for (int t = tid; t < 128 * K4; t += NT) {
        int c4 = t % K4;
        int r  = t / K4;
        int row = row0 + r;
        float4 x = make_float4(0.f, 0.f, 0.f, 0.f);
        if (row < limit)
            x = *reinterpret_cast<const float4*>(&src[(size_t)row * srcStride + srcOff + c4 * 4]);
        float* d = &sX[r * LD + c4 * 4];
        d[0] = x.x; d[1] = x.y; d[2] = x.z; d[3] = x.w;
    }
}

// ---- float4 loader for LD=40 ----------------------------------------------
template <int NT>
__device__ __forceinline__ void load_rm4_40(const float* __restrict__ src,
                                            int row0, int limit,
                                            float* __restrict__ sX, int tid) {
    for (int t = tid; t < 128 * 8; t += NT) {
        int c4 = t & 7;
        int r  = t >> 3;
        int row = row0 + r;
        float4 x = make_float4(0.f, 0.f, 0.f, 0.f);
        if (row < limit)
            x = *reinterpret_cast<const float4*>(&src[(size_t)row * 32 + c4 * 4]);
        *reinterpret_cast<float4*>(&sX[r * 40 + c4 * 4]) = x;
    }
}

// ---- 128x64 micro-kernels (proven) ----------------------------------------
template <int K, int LD>
__device__ __forceinline__ void mm8_rm(const float* __restrict__ sX,
                                       const float* __restrict__ sW,
                                       ull acc[8][4], int tx, int ty) {
    const int c0 = tx * 8, r0 = ty * 8;
#pragma unroll 8
    for (int k = 0; k < K; ++k) {
        ulonglong2 w0 = *reinterpret_cast<const ulonglong2*>(&sW[k * 64 + c0]);
        ulonglong2 w1 = *reinterpret_cast<const ulonglong2*>(&sW[k * 64 + c0 + 4]);
#pragma unroll
        for (int i = 0; i < 8; ++i) {
            float a = sX[(r0 + i) * LD + k];
            ull ap = pk2(a, a);
            acc[i][0] = fma2(ap, w0.x, acc[i][0]);
            acc[i][1] = fma2(ap, w0.y, acc[i][1]);
            acc[i][2] = fma2(ap, w1.x, acc[i][2]);
            acc[i][3] = fma2(ap, w1.y, acc[i][3]);
        }
    }
}
template <int K>
__device__ __forceinline__ void mm8_cm(const float* __restrict__ sXT,
                                       const float* __restrict__ sW,
                                       ull acc[8][4], int tx, int ty) {
    const int c0 = tx * 8, r0 = ty * 8;
#pragma unroll 8
    for (int k = 0; k < K; ++k) {
        ulonglong2 w0 = *reinterpret_cast<const ulonglong2*>(&sW[k * 64 + c0]);
        ulonglong2 w1 = *reinterpret_cast<const ulonglong2*>(&sW[k * 64 + c0 + 4]);
#pragma unroll
        for (int i = 0; i < 8; ++i) {
            float a = sXT[k * 128 + r0 + i];
            ull ap = pk2(a, a);
            acc[i][0] = fma2(ap, w0.x, acc[i][0]);
            acc[i][1] = fma2(ap, w0.y, acc[i][1]);
            acc[i][2] = fma2(ap, w1.x, acc[i][2]);
            acc[i][3] = fma2(ap, w1.y, acc[i][3]);
        }
    }
}

// ---- block stats reduction (128 thr, 8 cols/thread) -----------------------
__device__ __forceinline__ void stats_reduce8(float s[8], float q[8], int tid,
                                              float* sPart,
                                              float* gsum, float* gsq) {
    int lane = tid & 31, wrp = tid >> 5;
#pragma unroll
    for (int j = 0; j < 8; ++j) {
        s[j] += __shfl_xor_sync(0xffffffffu, s[j], 8);
        s[j] += __shfl_xor_sync(0xffffffffu, s[j], 16);
        q[j] += __shfl_xor_sync(0xffffffffu, q[j], 8);
        q[j] += __shfl_xor_sync(0xffffffffu, q[j], 16);
    }
    if (lane < 8) {
        int c0 = lane * 8;
#pragma unroll
        for (int j = 0; j < 8; ++j) {
            sPart[wrp * 128 + c0 + j] = s[j];
            sPart[wrp * 128 + 64 + c0 + j] = q[j];
        }
    }
    __syncthreads();
    if (tid < 128) {
        float t = 0.f;
#pragma unroll
        for (int w = 0; w < 4; ++w) t += sPart[w * 128 + tid];
        if (tid < 64) atomicAdd(gsum + tid, t);
        else          atomicAdd(gsq + (tid - 64), t);
    }
}

// ---------------------------------------------------------------------------
// front: seg expansion + accumulator zeroing + prep, one grid (validated R10)
__global__ __launch_bounds__(256) void k_front(const int* __restrict__ csr, int N,
                                               int segBlocks,
                                               const float* __restrict__ Wq,
                                               const float* __restrict__ bq,
                                               const float* __restrict__ Wk,
                                               const float* __restrict__ bk) {
    int bid = blockIdx.x;
    int tid = threadIdx.x;
    if (bid < segBlocks) {
        int n = bid * 256 + tid;
        if (n < N) {
            int s = csr[n], e = csr[n + 1];
            for (int v = s; v < e; ++v) g_seg[v] = n;
        }
        return;
    }
    if (bid < segBlocks + 4) {
        int t = (bid - segBlocks) * 256 + tid;
        if (t < 128) g_stats[128 + t] = 0.f;
        if (t < 1024) g_cov[t] = 0.f;
        if (t < 32) g_mu[t] = 0.f;
        if (t < 2) g_ctr[t] = 0;
        return;
    }
    // prep block
    __shared__ float sWq[64 * 64];
    __shared__ float sWk[64 * 65];
    __shared__ float sbq[64], sbk[64];
    for (int i = tid; i < 64 * 64; i += 256) sWq[i] = Wq[i];
    if (tid < 64) { sbq[tid] = bq[tid]; sbk[tid] = bk[tid]; }
    __syncthreads();
    int irow = tid >> 6;
    int jl   = tid & 63;
    for (int cc = 0; cc < 3; ++cc) {
        __syncthreads();
        for (int t = tid; t < 64 * 64; t += 256) {
            int jj = t >> 6, s = t & 63;
            sWk[jj * 65 + s] = Wk[(cc * 64 + jj) * 64 + s];
        }
        __syncthreads();
#pragma unroll 4
        for (int it = 0; it < 16; ++it) {
            int ii = it * 4 + irow;
            float a = 0.f;
#pragma unroll 8
            for (int s = 0; s < 64; ++s)
                a = fmaf(sWq[ii * 64 + s], sWk[jl * 65 + s], a);
            g_Acmb[ii * 192 + cc * 64 + jl] = a;
        }
        if (tid < 64) {
            float a = 0.f;
#pragma unroll 8
            for (int s = 0; s < 64; ++s) a = fmaf(sbq[s], sWk[tid * 65 + s], a);
            g_r0[cc * 64 + tid] = a;
        }
    }
    if (tid < 64) {
        float a = 0.f;
#pragma unroll 8
        for (int s = 0; s < 64; ++s) a = fmaf(sWq[tid * 64 + s], sbk[s], a);
        g_wc[tid] = a;
    }
    if (tid == 0) {
        float a = 0.f;
        for (int s = 0; s < 64; ++s) a = fmaf(sbq[s], sbk[s], a);
        g_c0[0] = a;
    }
}

// ---- SYRK + last-block bn1 finalize (validated R10) -----------------------
__global__ __launch_bounds__(256) void k_cov(const float* __restrict__ xproj, int V,
                                             const float* __restrict__ W1,
                                             const float* __restrict__ b1,
                                             const float* __restrict__ g1,
                                             const float* __restrict__ be1,
                                             float invV) {
    __shared__ __align__(16) float sX[128 * 40];
    __shared__ float sCov[1024];
    __shared__ float sMu[32];
    __shared__ int sLast;
    int tid = threadIdx.x;
    for (int t = tid; t < 1024; t += 256) sCov[t] = 0.f;
    if (tid < 32) sMu[tid] = 0.f;

    int i4 = tid & 7;
    int j4 = (tid >> 3) & 7;
    int rs = tid >> 6;
    ull acc[4][2] = {};
    float4 msum = make_float4(0.f, 0.f, 0.f, 0.f);
    int base = blockIdx.x * 512;

    for (int tile = 0; tile < 4; ++tile) {
        __syncthreads();
        load_rm4_40<256>(xproj, base + tile * 128, V, sX, tid);
        __syncthreads();
        int rbeg = rs * 32;
#pragma unroll 4
        for (int r = rbeg; r < rbeg + 32; ++r) {
            float4 a = *reinterpret_cast<const float4*>(&sX[r * 40 + i4 * 4]);
            float4 b = *reinterpret_cast<const float4*>(&sX[r * 40 + j4 * 4]);
            ull bp0 = pk2(b.x, b.y), bp1 = pk2(b.z, b.w);
            ull ap;
            ap = pk2(a.x, a.x); acc[0][0] = fma2(ap, bp0, acc[0][0]); acc[0][1] = fma2(ap, bp1, acc[0][1]);
            ap = pk2(a.y, a.y); acc[1][0] = fma2(ap, bp0, acc[1][0]); acc[1][1] = fma2(ap, bp1, acc[1][1]);
            ap = pk2(a.z, a.z); acc[2][0] = fma2(ap, bp0, acc[2][0]); acc[2][1] = fma2(ap, bp1, acc[2][1]);
            ap = pk2(a.w, a.w); acc[3][0] = fma2(ap, bp0, acc[3][0]); acc[3][1] = fma2(ap, bp1, acc[3][1]);
            if (j4 == 0) {
                msum.x += a.x; msum.y += a.y; msum.z += a.z; msum.w += a.w;
            }
        }
    }
#pragma unroll
    for (int ii = 0; ii < 4; ++ii) {
        float v0, v1, v2, v3;
        upk2(acc[ii][0], v0, v1);
        upk2(acc[ii][1], v2, v3);
        int rowc = (i4 * 4 + ii) * 32 + j4 * 4;
        atomicAdd(&sCov[rowc], v0);
        atomicAdd(&sCov[rowc + 1], v1);
        atomicAdd(&sCov[rowc + 2], v2);
        atomicAdd(&sCov[rowc + 3], v3);
    }
    if (j4 == 0) {
        atomicAdd(&sMu[i4 * 4 + 0], msum.x);
        atomicAdd(&sMu[i4 * 4 + 1], msum.y);
        atomicAdd(&sMu[i4 * 4 + 2], msum.z);
        atomicAdd(&sMu[i4 * 4 + 3], msum.w);
    }
    __syncthreads();
    for (int t = tid; t < 1024; t += 256) atomicAdd(&g_cov[t], sCov[t]);
    if (tid < 32) atomicAdd(&g_mu[tid], sMu[tid]);

    __threadfence();
    if (tid == 0) {
        int old = atomicAdd(&g_ctr[0], 1);
        sLast = (old == (int)gridDim.x - 1);
    }
    __syncthreads();
    if (!sLast) return;
    for (int t = tid; t < 1024; t += 256) sCov[t] = g_cov[t];
    if (tid < 32) sMu[tid] = g_mu[tid];
    __syncthreads();
    if (tid < 64) {
        float w[32];
#pragma unroll
        for (int s = 0; s < 32; ++s) w[s] = W1[s * 64 + tid];
        float wmu = 0.f;
#pragma unroll
        for (int s = 0; s < 32; ++s) wmu = fmaf(w[s], sMu[s], wmu);
        float quad = 0.f;
#pragma unroll 4
        for (int s = 0; s < 32; ++s) {
            float a = 0.f;
#pragma unroll
            for (int t = 0; t < 32; ++t) a = fmaf(sCov[s * 32 + t], w[t], a);
            quad = fmaf(w[s], a, quad);
        }
        float m = wmu * invV;
        float var = quad * invV - m * m;
        float mean = m + b1[tid];
        float sc = g1[tid] / sqrtf(var + 1e-5f);
        g_bn1[tid] = sc;
        g_bn1[64 + tid] = be1[tid] - mean * sc;
    }
}

// ---- fused MLP + last-block bn2 finalize (validated R10) ------------------
__global__ __launch_bounds__(128) void k_fused12(const float* __restrict__ xproj,
                                                 const float* __restrict__ b1,
                                                 const float* __restrict__ W1,
                                                 const float* __restrict__ W2,
                                                 const float* __restrict__ b2,
                                                 const float* __restrict__ g2,
                                                 const float* __restrict__ be2,
                                                 int V, float invV) {
    __shared__ __align__(16) float smA[64 * 128];
    __shared__ __align__(16) float sW2[64 * 64];
    __shared__ int sLast;
    float* sX  = smA;
    float* sW1 = smA + 128 * 33;
    float* h1T = smA;
    int tid = threadIdx.x;
    int row0 = blockIdx.x * 128;

    load_rm<32, 33, 128>(xproj, row0, V, 32, 0, sX, tid);
    for (int i = tid; i < 32 * 64; i += 128) sW1[i] = W1[i];
    for (int i = tid; i < 64 * 64; i += 128) sW2[i] = W2[i];
    __syncthreads();

    int tx = tid & 7, ty = tid >> 3;
    int c0 = tx * 8, r0 = ty * 8;
    ull acc[8][4] = {};
    mm8_rm<32, 33>(sX, sW1, acc, tx, ty);

    float bb[8], sc[8], sh[8];
#pragma unroll
    for (int j = 0; j < 8; ++j) {
        bb[j] = b1[c0 + j];
        sc[j] = g_bn1[c0 + j];
        sh[j] = g_bn1[64 + c0 + j];
    }
    float h[8][8];
#pragma unroll
    for (int i = 0; i < 8; ++i) {
#pragma unroll
        for (int jp = 0; jp < 4; ++jp) {
            float y0, y1;
            upk2(acc[i][jp], y0, y1);
            h[i][jp * 2]     = fmaxf(fmaf(y0 + bb[jp * 2],     sc[jp * 2],     sh[jp * 2]),     0.f);
            h[i][jp * 2 + 1] = fmaxf(fmaf(y1 + bb[jp * 2 + 1], sc[jp * 2 + 1], sh[jp * 2 + 1]), 0.f);
        }
    }
    __syncthreads();

#pragma unroll
    for (int j = 0; j < 8; ++j) {
        *reinterpret_cast<float4*>(&h1T[(c0 + j) * 128 + r0]) =
            make_float4(h[0][j], h[1][j], h[2][j], h[3][j]);
        *reinterpret_cast<float4*>(&h1T[(c0 + j) * 128 + r0 + 4]) =
            make_float4(h[4][j], h[5][j], h[6][j], h[7][j]);
    }
    __syncthreads();

    ull acc2[8][4] = {};
    mm8_cm<64>(h1T, sW2, acc2, tx, ty);
    __syncthreads();

    float b2v[8];
#pragma unroll
    for (int j = 0; j < 8; ++j) b2v[j] = b2[c0 + j];
    float s[8] = {}, q[8] = {};
#pragma unroll
    for (int i = 0; i < 8; ++i) {
        int row = row0 + r0 + i;
        float y[8];
#pragma unroll
        for (int jp = 0; jp < 4; ++jp) {
            upk2(acc2[i][jp], y[jp * 2], y[jp * 2 + 1]);
            y[jp * 2] += b2v[jp * 2]; y[jp * 2 + 1] += b2v[jp * 2 + 1];
        }
        if (row < V) {
            union { unsigned short us[8]; uint4 u; } pkv;
#pragma unroll
            for (int j = 0; j < 8; ++j) {
                __half hh = __float2half_rn(y[j]);
                pkv.us[j] = __half_as_ushort(hh);
                float yr = __half2float(hh);
                s[j] += yr; q[j] += yr * yr;
            }
            *reinterpret_cast<uint4*>(&g_Y2h[(size_t)row * 64 + c0]) = pkv.u;
        }
    }
    stats_reduce8(s, q, tid, smA, &g_stats[128], &g_stats[192]);

    __threadfence();
    if (tid == 0) {
        int old = atomicAdd(&g_ctr[1], 1);
        sLast = (old == (int)gridDim.x - 1);
    }
    __syncthreads();
    if (!sLast) return;
    if (tid < 64) {
        float mean = g_stats[128 + tid] * invV;
        float var  = g_stats[192 + tid] * invV - mean * mean;
        float scl = g2[tid] / sqrtf(var + 1e-5f);
        g_bn2[tid] = scl;
        g_bn2[64 + tid] = be2[tid] - mean * scl;
    }
}

// ---- R = x_main @ Acmb + r0 (y=0..2) ; y==3 blocks compute c --------------
__global__ __launch_bounds__(256) void k_R(const float* __restrict__ xmain, int N,
                                           int nb128) {
    int tid = threadIdx.x;
    if ((int)blockIdx.y == 3) {
        // c_n = x_main_n . wc + c0, warp-per-segment strided over grid.x
        int wrp = (int)blockIdx.x * 8 + (tid >> 5);
        int l = tid & 31;
        int stride = nb128 * 8;
        float wc0 = __ldg(&g_wc[l]), wc1 = __ldg(&g_wc[32 + l]);
        float cc0 = g_c0[0];
        for (int seg = wrp; seg < N; seg += stride) {
            float p = xmain[(size_t)seg * 64 + l] * wc0
                    + xmain[(size_t)seg * 64 + 32 + l] * wc1;
#pragma unroll
            for (int o = 16; o; o >>= 1) p += __shfl_xor_sync(0xffffffffu, p, o);
            if (l == 0) g_c[seg] = p + cc0;
        }
        return;
    }
    __shared__ __align__(16) float sX[128 * 33];
    __shared__ __align__(16) float sW[64 * 64];
    int row0 = blockIdx.x * 128;
    int jt = blockIdx.y;
    for (int i = tid; i < 64 * 64; i += 256) {
        int k = i >> 6, c = i & 63;
        sW[i] = g_Acmb[k * 192 + jt * 64 + c];
    }
    int tx = tid & 7, ty = tid >> 3;
    int c0 = tx * 8, r0 = ty * 4;
    ull acc[4][4] = {};
    load_rm<32, 33, 256>(xmain, row0, N, 64, 0, sX, tid);
    __syncthreads();
#pragma unroll 8
    for (int k = 0; k < 32; ++k) {
        ulonglong2 w0 = *reinterpret_cast<const ulonglong2*>(&sW[k * 64 + c0]);
        ulonglong2 w1 = *reinterpret_cast<const ulonglong2*>(&sW[k * 64 + c0 + 4]);
#pragma unroll
        for (int i = 0; i < 4; ++i) {
            float a = sX[(r0 + i) * 33 + k];
            ull ap = pk2(a, a);
            acc[i][0] = fma2(ap, w0.x, acc[i][0]);
            acc[i][1] = fma2(ap, w0.y, acc[i][1]);
            acc[i][2] = fma2(ap, w1.x, acc[i][2]);
            acc[i][3] = fma2(ap, w1.y, acc[i][3]);
        }
    }
    __syncthreads();
    load_rm<32, 33, 256>(xmain, row0, N, 64, 32, sX, tid);
    __syncthreads();
#pragma unroll 8
    for (int k = 0; k < 32; ++k) {
        ulonglong2 w0 = *reinterpret_cast<const ulonglong2*>(&sW[(k + 32) * 64 + c0]);
        ulonglong2 w1 = *reinterpret_cast<const ulonglong2*>(&sW[(k + 32) * 64 + c0 + 4]);
#pragma unroll
        for (int i = 0; i < 4; ++i) {
            float a = sX[(r0 + i) * 33 + k];
            ull ap = pk2(a, a);
            acc[i][0] = fma2(ap, w0.x, acc[i][0]);
            acc[i][1] = fma2(ap, w0.y, acc[i][1]);
            acc[i][2] = fma2(ap, w1.x, acc[i][2]);
            acc[i][3] = fma2(ap, w1.y, acc[i][3]);
        }
    }

    float bb[8];
#pragma unroll
    for (int j = 0; j < 8; ++j) bb[j] = g_r0[jt * 64 + c0 + j];
#pragma unroll
    for (int i = 0; i < 4; ++i) {
        int row = row0 + r0 + i;
        if (row < N) {
            float y[8];
#pragma unroll
            for (int jp = 0; jp < 4; ++jp) {
                upk2(acc[i][jp], y[jp * 2], y[jp * 2 + 1]);
                y[jp * 2] += bb[jp * 2]; y[jp * 2 + 1] += bb[jp * 2 + 1];
            }
            *reinterpret_cast<float4*>(&g_R[(size_t)row * 192 + jt * 64 + c0]) =
                make_float4(y[0], y[1], y[2], y[3]);
            *reinterpret_cast<float4*>(&g_R[(size_t)row * 192 + jt * 64 + c0 + 4]) =
                make_float4(y[4], y[5], y[6], y[7]);
        }
    }
}

// ---- X_v = h2_v . R_seg[0:64] + xmod_v . R_seg[64:192] + c_seg ------------
__global__ __launch_bounds__(256) void k_score(const float* __restrict__ xmod, int V) {
    int w = (blockIdx.x * blockDim.x + threadIdx.x) >> 5;
    int l = threadIdx.x & 31;
    if (w >= V) return;
    int sg = g_seg[w];
    const float* R = g_R + (size_t)sg * 192;
    float p = 0.f;
    {
        __half2 yp = *reinterpret_cast<const __half2*>(&g_Y2h[(size_t)w * 64 + 2 * l]);
        float y0 = __low2float(yp), y1 = __high2float(yp);
        int ca = 2 * l, cb = 2 * l + 1;
        float h0 = fmaxf(fmaf(y0, g_bn2[ca], g_bn2[64 + ca]), 0.f);
        float h1 = fmaxf(fmaf(y1, g_bn2[cb], g_bn2[64 + cb]), 0.f);
        p = fmaf(h0, __ldg(&R[ca]), p);
        p = fmaf(h1, __ldg(&R[cb]), p);
    }
#pragma unroll
    for (int j = 0; j < 4; ++j) {
        int c = l + 32 * j;
        p = fmaf(xmod[(size_t)w * 128 + c], __ldg(&R[64 + c]), p);
    }
#pragma unroll
    for (int o = 16; o; o >>= 1) p += __shfl_xor_sync(0xffffffffu, p, o);
    if (l == 0) g_X[w] = p + g_c[sg];
}

// ---- per-segment scaled softmax + weighted max-pool + gate ----------------
__global__ __launch_bounds__(256) void k_pool(const int* __restrict__ csr,
                                              const float* __restrict__ xmod,
                                              float* __restrict__ out,
                                              int N, int hasSeen) {
    int warp = (blockIdx.x * blockDim.x + threadIdx.x) >> 5;
    int lane = threadIdx.x & 31;
    if (warp >= N) return;
    int s = csr[warp], e = csr[warp + 1];
    int cnt = e - s;
    float* orow = out + (size_t)warp * 128;
    if (cnt <= 0) {
        orow[lane] = 0.f; orow[lane + 32] = 0.f;
        orow[lane + 64] = 0.f; orow[lane + 96] = 0.f;
        if (hasSeen && lane == 0) out[(size_t)N * 128 + warp] = 0.f;
        return;
    }
    const float NEG_INF = __int_as_float(0xff800000);
    float m = NEG_INF;
    for (int v = s + lane; v < e; v += 32) m = fmaxf(m, g_X[v]);
#pragma unroll
    for (int o = 16; o; o >>= 1) m = fmaxf(m, __shfl_xor_sync(0xffffffffu, m, o));
    float inv = rsqrtf((float)cnt);
    float ss = 0.f;
    for (int v = s + lane; v < e; v += 32) ss += expf((g_X[v] - m) * inv);
#pragma unroll
    for (int o = 16; o; o >>= 1) ss += __shfl_xor_sync(0xffffffffu, ss, o);
    float rden = 1.0f / (ss + 1e-12f);
    float G = tanhf(fmaxf(m, 0.f));
    float p0 = NEG_INF, p1 = NEG_INF, p2 = NEG_INF, p3 = NEG_INF;
    int v = s;
    for (; v + 1 < e; v += 2) {
        float a0 = expf((g_X[v] - m) * inv) * rden;
        float a1 = expf((g_X[v + 1] - m) * inv) * rden;
        const float* x0 = xmod + (size_t)v * 128;
        const float* x1 = x0 + 128;
        float u0 = x0[lane], u1 = x0[lane + 32], u2 = x0[lane + 64], u3 = x0[lane + 96];
        float w0 = x1[lane], w1 = x1[lane + 32], w2 = x1[lane + 64], w3 = x1[lane + 96];
        p0 = fmaxf(p0, fmaxf(u0 * a0, w0 * a1));
        p1 = fmaxf(p1, fmaxf(u1 * a0, w1 * a1));
        p2 = fmaxf(p2, fmaxf(u2 * a0, w2 * a1));
        p3 = fmaxf(p3, fmaxf(u3 * a0, w3 * a1));
    }
    if (v < e) {
        float a = expf((g_X[v] - m) * inv) * rden;
        const float* xr = xmod + (size_t)v * 128;
        p0 = fmaxf(p0, xr[lane] * a);
        p1 = fmaxf(p1, xr[lane + 32] * a);
        p2 = fmaxf(p2, xr[lane + 64] * a);
        p3 = fmaxf(p3, xr[lane + 96] * a);
    }
    orow[lane]      = p0 * G;
    orow[lane + 32] = p1 * G;
    orow[lane + 64] = p2 * G;
    orow[lane + 96] = p3 * G;
    if (hasSeen && lane == 0) out[(size_t)N * 128 + warp] = 1.f;
}

// ---------------------------------------------------------------------------
extern "C" void kernel_launch(void* const* d_in, const int* in_sizes, int n_in,
                              void* d_out, int out_size) {
    const float* x_main = (const float*)d_in[0];
    const float* x_mod  = (const float*)d_in[1];
    const float* x_proj = (const float*)d_in[2];
    const int*   csr    = (const int*)d_in[3];
    const float* Wq = (const float*)d_in[4];
    const float* bq = (const float*)d_in[5];
    const float* W1 = (const float*)d_in[6];
    const float* b1 = (const float*)d_in[7];
    const float* g1 = (const float*)d_in[8];
    const float* be1 = (const float*)d_in[9];
    const float* W2 = (const float*)d_in[10];
    const float* b2 = (const float*)d_in[11];
    const float* g2 = (const float*)d_in[12];
    const float* be2 = (const float*)d_in[13];
    const float* Wk = (const float*)d_in[14];
    const float* bk = (const float*)d_in[15];

    int N = in_sizes[0] / 64;
    int V = in_sizes[1] / 128;
    float* out = (float*)d_out;
    int hasSeen = (out_size >= N * 129) ? 1 : 0;
    float invV = 1.0f / (float)V;

    int vb128 = (V + 127) / 128;
    int nb128 = (N + 127) / 128;
    int segBlocks = (N + 255) / 256;

    k_front<<<segBlocks + 5, 256>>>(csr, N, segBlocks, Wq, bq, Wk, bk);
    k_cov<<<(V + 511) / 512, 256>>>(x_proj, V, W1, b1, g1, be1, invV);
    k_fused12<<<vb128, 128>>>(x_proj, b1, W1, W2, b2, g2, be2, V, invV);
    {
        dim3 g(nb128, 4);
        k_R<<<g, 256>>>(x_main, N, nb128);
    }
    k_score<<<(V * 32 + 255) / 256, 256>>>(x_mod, V);
    k_pool<<<(N * 32 + 255) / 256, 256>>>(csr, x_mod, out, N, hasSeen);
}

// round 16
// speedup vs baseline: 1.8495x; 1.8495x over previous
#include <cuda_runtime.h>
#include <cuda_fp16.h>
#include <math.h>

// ---------------------------------------------------------------------------
// AttentiveBimodalCSRPool — round 16.
//   R9 base verbatim (best 889us) with ONE change: k_c/k_score/k_pool
//   replaced by k_spool (online softmax+maxpool, 2-row-unrolled shuffle
//   reduction). g_seg/g_X/g_c eliminated. Launch consolidation NOT used
//   (R15 showed it costs ~+300us via register pressure / grid merging).
// ---------------------------------------------------------------------------

#define MAXV 1000000
#define MAXN 125056
typedef unsigned long long ull;

__device__ __align__(16) unsigned short g_Y2h[(size_t)MAXV * 64];  // fp16
__device__ float g_R[(size_t)MAXN * 192];
__device__ float g_stats[256];    // [128..191]=sum2, [192..255]=sq2
__device__ float g_cov[32 * 32];
__device__ float g_mu[32];
__device__ float g_bn1[128];      // [scale(64), shift(64)]
__device__ float g_bn2[128];
__device__ float g_Acmb[64 * 192];
__device__ float g_r0[192];
__device__ float g_wc[64];
__device__ float g_c0[1];

// ---- packed f32x2 helpers -------------------------------------------------
__device__ __forceinline__ ull pk2(float lo, float hi) {
    ull r; asm("mov.b64 %0, {%1, %2};" : "=l"(r) : "f"(lo), "f"(hi)); return r;
}
__device__ __forceinline__ ull fma2(ull a, ull b, ull c) {
    ull d; asm("fma.rn.f32x2 %0, %1, %2, %3;" : "=l"(d) : "l"(a), "l"(b), "l"(c));
    return d;
}
__device__ __forceinline__ void upk2(ull v, float& lo, float& hi) {
    asm("mov.b64 {%0, %1}, %2;" : "=f"(lo), "=f"(hi) : "l"(v));
}

// ---- row-major tile loader: sX[r][k], LD odd => conflict-free -------------
template <int K, int LD, int NT>
__device__ __forceinline__ void load_rm(const float* __restrict__ src,
                                        int row0, int limit,
                                        int srcStride, int srcOff,
                                        float* __restrict__ sX, int tid) {
    constexpr int K4 = K / 4;
    for (int t = tid; t < 128 * K4; t += NT) {
        int c4 = t % K4;
        int r  = t / K4;
        int row = row0 + r;
        float4 x = make_float4(0.f, 0.f, 0.f, 0.f);
        if (row < limit)
            x = *reinterpret_cast<const float4*>(&src[(size_t)row * srcStride + srcOff + c4 * 4]);
        float* d = &sX[r * LD + c4 * 4];
        d[0] = x.x; d[1] = x.y; d[2] = x.z; d[3] = x.w;
    }
}

// ---- float4 loader for LD=40 ----------------------------------------------
template <int NT>
__device__ __forceinline__ void load_rm4_40(const float* __restrict__ src,
                                            int row0, int limit,
                                            float* __restrict__ sX, int tid) {
    for (int t = tid; t < 128 * 8; t += NT) {
        int c4 = t & 7;
        int r  = t >> 3;
        int row = row0 + r;
        float4 x = make_float4(0.f, 0.f, 0.f, 0.f);
        if (row < limit)
            x = *reinterpret_cast<const float4*>(&src[(size_t)row * 32 + c4 * 4]);
        *reinterpret_cast<float4*>(&sX[r * 40 + c4 * 4]) = x;
    }
}

// ---- 128x64 micro-kernels (proven) ----------------------------------------
template <int K, int LD>
__device__ __forceinline__ void mm8_rm(const float* __restrict__ sX,
                                       const float* __restrict__ sW,
                                       ull acc[8][4], int tx, int ty) {
    const int c0 = tx * 8, r0 = ty * 8;
#pragma unroll 8
    for (int k = 0; k < K; ++k) {
        ulonglong2 w0 = *reinterpret_cast<const ulonglong2*>(&sW[k * 64 + c0]);
        ulonglong2 w1 = *reinterpret_cast<const ulonglong2*>(&sW[k * 64 + c0 + 4]);
#pragma unroll
        for (int i = 0; i < 8; ++i) {
            float a = sX[(r0 + i) * LD + k];
            ull ap = pk2(a, a);
            acc[i][0] = fma2(ap, w0.x, acc[i][0]);
            acc[i][1] = fma2(ap, w0.y, acc[i][1]);
            acc[i][2] = fma2(ap, w1.x, acc[i][2]);
            acc[i][3] = fma2(ap, w1.y, acc[i][3]);
        }
    }
}
template <int K>
__device__ __forceinline__ void mm8_cm(const float* __restrict__ sXT,
                                       const float* __restrict__ sW,
                                       ull acc[8][4], int tx, int ty) {
    const int c0 = tx * 8, r0 = ty * 8;
#pragma unroll 8
    for (int k = 0; k < K; ++k) {
        ulonglong2 w0 = *reinterpret_cast<const ulonglong2*>(&sW[k * 64 + c0]);
        ulonglong2 w1 = *reinterpret_cast<const ulonglong2*>(&sW[k * 64 + c0 + 4]);
#pragma unroll
        for (int i = 0; i < 8; ++i) {
            float a = sXT[k * 128 + r0 + i];
            ull ap = pk2(a, a);
            acc[i][0] = fma2(ap, w0.x, acc[i][0]);
            acc[i][1] = fma2(ap, w0.y, acc[i][1]);
            acc[i][2] = fma2(ap, w1.x, acc[i][2]);
            acc[i][3] = fma2(ap, w1.y, acc[i][3]);
        }
    }
}

// ---- block stats reduction (128 thr, 8 cols/thread) -----------------------
__device__ __forceinline__ void stats_reduce8(float s[8], float q[8], int tid,
                                              float* sPart,
                                              float* gsum, float* gsq) {
    int lane = tid & 31, wrp = tid >> 5;
#pragma unroll
    for (int j = 0; j < 8; ++j) {
        s[j] += __shfl_xor_sync(0xffffffffu, s[j], 8);
        s[j] += __shfl_xor_sync(0xffffffffu, s[j], 16);
        q[j] += __shfl_xor_sync(0xffffffffu, q[j], 8);
        q[j] += __shfl_xor_sync(0xffffffffu, q[j], 16);
    }
    if (lane < 8) {
        int c0 = lane * 8;
#pragma unroll
        for (int j = 0; j < 8; ++j) {
            sPart[wrp * 128 + c0 + j] = s[j];
            sPart[wrp * 128 + 64 + c0 + j] = q[j];
        }
    }
    __syncthreads();
    if (tid < 128) {
        float t = 0.f;
#pragma unroll
        for (int w = 0; w < 4; ++w) t += sPart[w * 128 + tid];
        if (tid < 64) atomicAdd(gsum + tid, t);
        else          atomicAdd(gsq + (tid - 64), t);
    }
}

// ---------------------------------------------------------------------------
__global__ void k_zero() {
    int t = threadIdx.x + blockIdx.x * blockDim.x;
    if (t < 128) g_stats[128 + t] = 0.f;
    if (t < 1024) g_cov[t] = 0.f;
    if (t < 32) g_mu[t] = 0.f;
}

// ---- combined weights: Acmb = Wq@Wk^T, r0, wc, c0 -------------------------
__global__ __launch_bounds__(256) void k_prep(const float* __restrict__ Wq,
                                              const float* __restrict__ bq,
                                              const float* __restrict__ Wk,
                                              const float* __restrict__ bk) {
    __shared__ float sWq[64 * 64];
    __shared__ float sWk[64 * 65];
    __shared__ float sbq[64], sbk[64];
    int tid = threadIdx.x;
    for (int i = tid; i < 64 * 64; i += 256) sWq[i] = Wq[i];
    if (tid < 64) { sbq[tid] = bq[tid]; sbk[tid] = bk[tid]; }
    __syncthreads();
    int irow = tid >> 6;
    int jl   = tid & 63;
    for (int cc = 0; cc < 3; ++cc) {
        __syncthreads();
        for (int t = tid; t < 64 * 64; t += 256) {
            int jj = t >> 6, s = t & 63;
            sWk[jj * 65 + s] = Wk[(cc * 64 + jj) * 64 + s];
        }
        __syncthreads();
#pragma unroll 4
        for (int it = 0; it < 16; ++it) {
            int ii = it * 4 + irow;
            float a = 0.f;
#pragma unroll 8
            for (int s = 0; s < 64; ++s)
                a = fmaf(sWq[ii * 64 + s], sWk[jl * 65 + s], a);
            g_Acmb[ii * 192 + cc * 64 + jl] = a;
        }
        if (tid < 64) {
            float a = 0.f;
#pragma unroll 8
            for (int s = 0; s < 64; ++s) a = fmaf(sbq[s], sWk[tid * 65 + s], a);
            g_r0[cc * 64 + tid] = a;
        }
    }
    if (tid < 64) {
        float a = 0.f;
#pragma unroll 8
        for (int s = 0; s < 64; ++s) a = fmaf(sWq[tid * 64 + s], sbk[s], a);
        g_wc[tid] = a;
    }
    if (tid == 0) {
        float a = 0.f;
        for (int s = 0; s < 64; ++s) a = fmaf(sbq[s], sbk[s], a);
        g_c0[0] = a;
    }
}

// ---- SYRK via LDS.128: g_cov += x^T x, g_mu += colsum ---------------------
__global__ __launch_bounds__(256) void k_cov(const float* __restrict__ xproj, int V) {
    __shared__ __align__(16) float sX[128 * 40];
    __shared__ float sCov[1024];
    __shared__ float sMu[32];
    int tid = threadIdx.x;
    for (int t = tid; t < 1024; t += 256) sCov[t] = 0.f;
    if (tid < 32) sMu[tid] = 0.f;

    int i4 = tid & 7;
    int j4 = (tid >> 3) & 7;
    int rs = tid >> 6;
    ull acc[4][2] = {};
    float4 msum = make_float4(0.f, 0.f, 0.f, 0.f);
    int base = blockIdx.x * 512;

    for (int tile = 0; tile < 4; ++tile) {
        __syncthreads();
        load_rm4_40<256>(xproj, base + tile * 128, V, sX, tid);
        __syncthreads();
        int rbeg = rs * 32;
#pragma unroll 4
        for (int r = rbeg; r < rbeg + 32; ++r) {
            float4 a = *reinterpret_cast<const float4*>(&sX[r * 40 + i4 * 4]);
            float4 b = *reinterpret_cast<const float4*>(&sX[r * 40 + j4 * 4]);
            ull bp0 = pk2(b.x, b.y), bp1 = pk2(b.z, b.w);
            ull ap;
            ap = pk2(a.x, a.x); acc[0][0] = fma2(ap, bp0, acc[0][0]); acc[0][1] = fma2(ap, bp1, acc[0][1]);
            ap = pk2(a.y, a.y); acc[1][0] = fma2(ap, bp0, acc[1][0]); acc[1][1] = fma2(ap, bp1, acc[1][1]);
            ap = pk2(a.z, a.z); acc[2][0] = fma2(ap, bp0, acc[2][0]); acc[2][1] = fma2(ap, bp1, acc[2][1]);
            ap = pk2(a.w, a.w); acc[3][0] = fma2(ap, bp0, acc[3][0]); acc[3][1] = fma2(ap, bp1, acc[3][1]);
            if (j4 == 0) {
                msum.x += a.x; msum.y += a.y; msum.z += a.z; msum.w += a.w;
            }
        }
    }
#pragma unroll
    for (int ii = 0; ii < 4; ++ii) {
        float v0, v1, v2, v3;
        upk2(acc[ii][0], v0, v1);
        upk2(acc[ii][1], v2, v3);
        int rowc = (i4 * 4 + ii) * 32 + j4 * 4;
        atomicAdd(&sCov[rowc], v0);
        atomicAdd(&sCov[rowc + 1], v1);
        atomicAdd(&sCov[rowc + 2], v2);
        atomicAdd(&sCov[rowc + 3], v3);
    }
    if (j4 == 0) {
        atomicAdd(&sMu[i4 * 4 + 0], msum.x);
        atomicAdd(&sMu[i4 * 4 + 1], msum.y);
        atomicAdd(&sMu[i4 * 4 + 2], msum.z);
        atomicAdd(&sMu[i4 * 4 + 3], msum.w);
    }
    __syncthreads();
    for (int t = tid; t < 1024; t += 256) atomicAdd(&g_cov[t], sCov[t]);
    if (tid < 32) atomicAdd(&g_mu[tid], sMu[tid]);
}

// ---- finalize bn1 from covariance -----------------------------------------
__global__ __launch_bounds__(64) void k_fin1(const float* __restrict__ W1,
                                             const float* __restrict__ b1,
                                             const float* __restrict__ g1,
                                             const float* __restrict__ be1,
                                             float invV) {
    __shared__ float sS[1024];
    __shared__ float sMu[32];
    int tid = threadIdx.x;
    for (int t = tid; t < 1024; t += 64) sS[t] = g_cov[t];
    if (tid < 32) sMu[tid] = g_mu[tid];
    __syncthreads();
    float w[32];
#pragma unroll
    for (int s = 0; s < 32; ++s) w[s] = W1[s * 64 + tid];
    float wmu = 0.f;
#pragma unroll
    for (int s = 0; s < 32; ++s) wmu = fmaf(w[s], sMu[s], wmu);
    float quad = 0.f;
#pragma unroll 4
    for (int s = 0; s < 32; ++s) {
        float acc = 0.f;
#pragma unroll
        for (int t = 0; t < 32; ++t) acc = fmaf(sS[s * 32 + t], w[t], acc);
        quad = fmaf(w[s], acc, quad);
    }
    float m = wmu * invV;
    float var = quad * invV - m * m;
    float mean = m + b1[tid];
    float sc = g1[tid] / sqrtf(var + 1e-5f);
    g_bn1[tid] = sc;
    g_bn1[64 + tid] = be1[tid] - mean * sc;
}

__global__ void k_finalize2(const float* __restrict__ gg,
                            const float* __restrict__ bb, float invV) {
    int c = threadIdx.x;
    if (c >= 64) return;
    float mean = g_stats[128 + c] * invV;
    float var  = g_stats[192 + c] * invV - mean * mean;
    float sc = gg[c] / sqrtf(var + 1e-5f);
    g_bn2[c] = sc;
    g_bn2[64 + c] = bb[c] - mean * sc;
}

// ---- fused: x_proj -> Y1 -> bn1/relu -> @W2 -> Y2(fp16) (+stats2) ---------
__global__ __launch_bounds__(128) void k_fused12(const float* __restrict__ xproj,
                                                 const float* __restrict__ b1,
                                                 const float* __restrict__ W1,
                                                 const float* __restrict__ W2,
                                                 const float* __restrict__ b2, int V) {
    __shared__ __align__(16) float smA[64 * 128];
    __shared__ __align__(16) float sW2[64 * 64];
    float* sX  = smA;
    float* sW1 = smA + 128 * 33;
    float* h1T = smA;
    int tid = threadIdx.x;
    int row0 = blockIdx.x * 128;

    load_rm<32, 33, 128>(xproj, row0, V, 32, 0, sX, tid);
    for (int i = tid; i < 32 * 64; i += 128) sW1[i] = W1[i];
    for (int i = tid; i < 64 * 64; i += 128) sW2[i] = W2[i];
    __syncthreads();

    int tx = tid & 7, ty = tid >> 3;
    int c0 = tx * 8, r0 = ty * 8;
    ull acc[8][4] = {};
    mm8_rm<32, 33>(sX, sW1, acc, tx, ty);

    float bb[8], sc[8], sh[8];
#pragma unroll
    for (int j = 0; j < 8; ++j) {
        bb[j] = b1[c0 + j];
        sc[j] = g_bn1[c0 + j];
        sh[j] = g_bn1[64 + c0 + j];
    }
    float h[8][8];
#pragma unroll
    for (int i = 0; i < 8; ++i) {
#pragma unroll
        for (int jp = 0; jp < 4; ++jp) {
            float y0, y1;
            upk2(acc[i][jp], y0, y1);
            h[i][jp * 2]     = fmaxf(fmaf(y0 + bb[jp * 2],     sc[jp * 2],     sh[jp * 2]),     0.f);
            h[i][jp * 2 + 1] = fmaxf(fmaf(y1 + bb[jp * 2 + 1], sc[jp * 2 + 1], sh[jp * 2 + 1]), 0.f);
        }
    }
    __syncthreads();

#pragma unroll
    for (int j = 0; j < 8; ++j) {
        *reinterpret_cast<float4*>(&h1T[(c0 + j) * 128 + r0]) =
            make_float4(h[0][j], h[1][j], h[2][j], h[3][j]);
        *reinterpret_cast<float4*>(&h1T[(c0 + j) * 128 + r0 + 4]) =
            make_float4(h[4][j], h[5][j], h[6][j], h[7][j]);
    }
    __syncthreads();

    ull acc2[8][4] = {};
    mm8_cm<64>(h1T, sW2, acc2, tx, ty);
    __syncthreads();

    float b2v[8];
#pragma unroll
    for (int j = 0; j < 8; ++j) b2v[j] = b2[c0 + j];
    float s[8] = {}, q[8] = {};
#pragma unroll
    for (int i = 0; i < 8; ++i) {
        int row = row0 + r0 + i;
        float y[8];
#pragma unroll
        for (int jp = 0; jp < 4; ++jp) {
            upk2(acc2[i][jp], y[jp * 2], y[jp * 2 + 1]);
            y[jp * 2] += b2v[jp * 2]; y[jp * 2 + 1] += b2v[jp * 2 + 1];
        }
        if (row < V) {
            union { unsigned short us[8]; uint4 u; } pkv;
#pragma unroll
            for (int j = 0; j < 8; ++j) {
                __half hh = __float2half_rn(y[j]);
                pkv.us[j] = __half_as_ushort(hh);
                float yr = __half2float(hh);
                s[j] += yr; q[j] += yr * yr;
            }
            *reinterpret_cast<uint4*>(&g_Y2h[(size_t)row * 64 + c0]) = pkv.u;
        }
    }
    stats_reduce8(s, q, tid, smA, &g_stats[128], &g_stats[192]);
}

// ---- R = x_main @ Acmb + r0 (R9's 128-thread version, proven) -------------
__global__ __launch_bounds__(128) void k_R(const float* __restrict__ xmain, int N) {
    __shared__ __align__(16) float sX[128 * 33];
    __shared__ __align__(16) float sW[64 * 64];
    int tid = threadIdx.x;
    int row0 = blockIdx.x * 128;
    int jt = blockIdx.y;
    for (int i = tid; i < 64 * 64; i += 128) {
        int k = i >> 6, c = i & 63;
        sW[i] = g_Acmb[k * 192 + jt * 64 + c];
    }
    int tx = tid & 7, ty = tid >> 3;
    int c0 = tx * 8, r0 = ty * 8;
    ull acc[8][4] = {};
    load_rm<32, 33, 128>(xmain, row0, N, 64, 0, sX, tid);
    __syncthreads();
    mm8_rm<32, 33>(sX, sW, acc, tx, ty);
    __syncthreads();
    load_rm<32, 33, 128>(xmain, row0, N, 64, 32, sX, tid);
    __syncthreads();
    mm8_rm<32, 33>(sX, sW + 32 * 64, acc, tx, ty);

    float bb[8];
#pragma unroll
    for (int j = 0; j < 8; ++j) bb[j] = g_r0[jt * 64 + c0 + j];
#pragma unroll
    for (int i = 0; i < 8; ++i) {
        int row = row0 + r0 + i;
        if (row < N) {
            float y[8];
#pragma unroll
            for (int jp = 0; jp < 4; ++jp) {
                upk2(acc[i][jp], y[jp * 2], y[jp * 2 + 1]);
                y[jp * 2] += bb[jp * 2]; y[jp * 2 + 1] += bb[jp * 2 + 1];
            }
            *reinterpret_cast<float4*>(&g_R[(size_t)row * 192 + jt * 64 + c0]) =
                make_float4(y[0], y[1], y[2], y[3]);
            *reinterpret_cast<float4*>(&g_R[(size_t)row * 192 + jt * 64 + c0 + 4]) =
                make_float4(y[4], y[5], y[6], y[7]);
        }
    }
}

// ---- fused score+softmax+maxpool (warp/segment, 2-row unrolled) -----------
__global__ __launch_bounds__(256) void k_spool(const int* __restrict__ csr,
                                               const float* __restrict__ xmain,
                                               const float* __restrict__ xmod,
                                               float* __restrict__ out,
                                               int N, int hasSeen) {
    int seg = (blockIdx.x * blockDim.x + threadIdx.x) >> 5;
    int lane = threadIdx.x & 31;
    if (seg >= N) return;
    int s = csr[seg], e = csr[seg + 1];
    int cnt = e - s;
    float* orow = out + (size_t)seg * 128;
    if (cnt <= 0) {
        orow[lane] = 0.f; orow[lane + 32] = 0.f;
        orow[lane + 64] = 0.f; orow[lane + 96] = 0.f;
        if (hasSeen && lane == 0) out[(size_t)N * 128 + seg] = 0.f;
        return;
    }

    // c_n = x_main . wc + c0
    float cn = xmain[(size_t)seg * 64 + lane] * __ldg(&g_wc[lane])
             + xmain[(size_t)seg * 64 + 32 + lane] * __ldg(&g_wc[32 + lane]);
#pragma unroll
    for (int o = 16; o; o >>= 1) cn += __shfl_xor_sync(0xffffffffu, cn, o);
    cn += g_c0[0];

    // per-segment R and bn2 registers
    const float* R = g_R + (size_t)seg * 192;
    int ca = 2 * lane, cb = ca + 1;
    float rA0 = __ldg(&R[ca]), rA1 = __ldg(&R[cb]);
    float rB0 = __ldg(&R[64 + lane]),  rB1 = __ldg(&R[96 + lane]);
    float rB2 = __ldg(&R[128 + lane]), rB3 = __ldg(&R[160 + lane]);
    float sc0 = __ldg(&g_bn2[ca]), sc1 = __ldg(&g_bn2[cb]);
    float sh0 = __ldg(&g_bn2[64 + ca]), sh1 = __ldg(&g_bn2[64 + cb]);

    const float NEG_INF = __int_as_float(0xff800000);
    float inv = rsqrtf((float)cnt);
    float m = NEG_INF, denom = 0.f;
    float p0 = NEG_INF, p1 = NEG_INF, p2 = NEG_INF, p3 = NEG_INF;

    int v = s;
    for (; v + 1 < e; v += 2) {
        // row v
        __half2 ypA = *reinterpret_cast<const __half2*>(&g_Y2h[(size_t)v * 64 + ca]);
        const float* xrA = xmod + (size_t)v * 128;
        float a0 = xrA[lane], a1 = xrA[lane + 32], a2 = xrA[lane + 64], a3 = xrA[lane + 96];
        float hA0 = fmaxf(fmaf(__low2float(ypA), sc0, sh0), 0.f);
        float hA1 = fmaxf(fmaf(__high2float(ypA), sc1, sh1), 0.f);
        float pa = hA0 * rA0 + hA1 * rA1 + a0 * rB0 + a1 * rB1 + a2 * rB2 + a3 * rB3;
        // row v+1
        __half2 ypB = *reinterpret_cast<const __half2*>(&g_Y2h[(size_t)(v + 1) * 64 + ca]);
        const float* xrB = xrA + 128;
        float b0 = xrB[lane], b1 = xrB[lane + 32], b2 = xrB[lane + 64], b3 = xrB[lane + 96];
        float hB0 = fmaxf(fmaf(__low2float(ypB), sc0, sh0), 0.f);
        float hB1 = fmaxf(fmaf(__high2float(ypB), sc1, sh1), 0.f);
        float pb = hB0 * rA0 + hB1 * rA1 + b0 * rB0 + b1 * rB1 + b2 * rB2 + b3 * rB3;
        // interleaved reductions (two independent chains)
#pragma unroll
        for (int o = 16; o; o >>= 1) {
            pa += __shfl_xor_sync(0xffffffffu, pa, o);
            pb += __shfl_xor_sync(0xffffffffu, pb, o);
        }
        float XA = pa + cn, XB = pb + cn;
        // online update row A
        if (XA <= m) {
            float ew = expf((XA - m) * inv);
            denom += ew;
            p0 = fmaxf(p0, a0 * ew); p1 = fmaxf(p1, a1 * ew);
            p2 = fmaxf(p2, a2 * ew); p3 = fmaxf(p3, a3 * ew);
        } else {
            float f = expf((m - XA) * inv);
            denom = denom * f + 1.f;
            p0 = fmaxf(p0 * f, a0); p1 = fmaxf(p1 * f, a1);
            p2 = fmaxf(p2 * f, a2); p3 = fmaxf(p3 * f, a3);
            m = XA;
        }
        // online update row B
        if (XB <= m) {
            float ew = expf((XB - m) * inv);
            denom += ew;
            p0 = fmaxf(p0, b0 * ew); p1 = fmaxf(p1, b1 * ew);
            p2 = fmaxf(p2, b2 * ew); p3 = fmaxf(p3, b3 * ew);
        } else {
            float f = expf((m - XB) * inv);
            denom = denom * f + 1.f;
            p0 = fmaxf(p0 * f, b0); p1 = fmaxf(p1 * f, b1);
            p2 = fmaxf(p2 * f, b2); p3 = fmaxf(p3 * f, b3);
            m = XB;
        }
    }
    if (v < e) {
        __half2 yp = *reinterpret_cast<const __half2*>(&g_Y2h[(size_t)v * 64 + ca]);
        const float* xr = xmod + (size_t)v * 128;
        float a0 = xr[lane], a1 = xr[lane + 32], a2 = xr[lane + 64], a3 = xr[lane + 96];
        float h0 = fmaxf(fmaf(__low2float(yp), sc0, sh0), 0.f);
        float h1 = fmaxf(fmaf(__high2float(yp), sc1, sh1), 0.f);
        float pa = h0 * rA0 + h1 * rA1 + a0 * rB0 + a1 * rB1 + a2 * rB2 + a3 * rB3;
#pragma unroll
        for (int o = 16; o; o >>= 1) pa += __shfl_xor_sync(0xffffffffu, pa, o);
        float XA = pa + cn;
        if (XA <= m) {
            float ew = expf((XA - m) * inv);
            denom += ew;
            p0 = fmaxf(p0, a0 * ew); p1 = fmaxf(p1, a1 * ew);
            p2 = fmaxf(p2, a2 * ew); p3 = fmaxf(p3, a3 * ew);
        } else {
            float f = expf((m - XA) * inv);
            denom = denom * f + 1.f;
            p0 = fmaxf(p0 * f, a0); p1 = fmaxf(p1 * f, a1);
            p2 = fmaxf(p2 * f, a2); p3 = fmaxf(p3 * f, a3);
            m = XA;
        }
    }
    float rden = 1.0f / (denom + 1e-12f);
    float G = tanhf(fmaxf(m, 0.f)) * rden;
    orow[lane]      = p0 * G;
    orow[lane + 32] = p1 * G;
    orow[lane + 64] = p2 * G;
    orow[lane + 96] = p3 * G;
    if (hasSeen && lane == 0) out[(size_t)N * 128 + seg] = 1.f;
}

// ---------------------------------------------------------------------------
extern "C" void kernel_launch(void* const* d_in, const int* in_sizes, int n_in,
                              void* d_out, int out_size) {
    const float* x_main = (const float*)d_in[0];
    const float* x_mod  = (const float*)d_in[1];
    const float* x_proj = (const float*)d_in[2];
    const int*   csr    = (const int*)d_in[3];
    const float* Wq = (const float*)d_in[4];
    const float* bq = (const float*)d_in[5];
    const float* W1 = (const float*)d_in[6];
    const float* b1 = (const float*)d_in[7];
    const float* g1 = (const float*)d_in[8];
    const float* be1 = (const float*)d_in[9];
    const float* W2 = (const float*)d_in[10];
    const float* b2 = (const float*)d_in[11];
    const float* g2 = (const float*)d_in[12];
    const float* be2 = (const float*)d_in[13];
    const float* Wk = (const float*)d_in[14];
    const float* bk = (const float*)d_in[15];

    int N = in_sizes[0] / 64;
    int V = in_sizes[1] / 128;
    float* out = (float*)d_out;
    int hasSeen = (out_size >= N * 129) ? 1 : 0;
    float invV = 1.0f / (float)V;

    int vb128 = (V + 127) / 128;
    int nb128 = (N + 127) / 128;

    k_zero<<<4, 256>>>();
    k_prep<<<1, 256>>>(Wq, bq, Wk, bk);
    k_cov<<<(V + 511) / 512, 256>>>(x_proj, V);
    k_fin1<<<1, 64>>>(W1, b1, g1, be1, invV);
    k_fused12<<<vb128, 128>>>(x_proj, b1, W1, W2, b2, V);
    k_finalize2<<<1, 64>>>(g2, be2, invV);
    {
        dim3 g(nb128, 3);
        k_R<<<g, 128>>>(x_main, N);
    }
    k_spool<<<(N * 32 + 255) / 256, 256>>>(csr, x_main, x_mod, out, N, hasSeen);
}